// round 11
// baseline (speedup 1.0000x reference)
#include <cuda_runtime.h>
#include <cuda_bf16.h>
#include <math.h>
#include <stdint.h>

// ----------------------------------------------------------------------------
// MemoryNetwork, GB300 sm_103a (PTX target sm_103 => family-portable ISA only)
//
//   M1[d,m,:] = W_topic  @ mems_d[d,m]; M2 likewise (rows 0..95 topic, 96..191 domain)
//   P[b,r]    = feature_b . M[r]   via mma.sync bf16 hi/lo split (3 passes, fp32 acc)
//   fused row-norm + topic softmax + domain softmax epilogue.
//
// R10: fused = M=64/256thr/2CTA-per-SM (best-measured occupancy) + KC=32
//      double-buffer + mma-first schedule (best-measured cycle count).
//      build_M = no split-K, no W redundancy: 128 blocks x 96 rows, ~10us.
// ----------------------------------------------------------------------------

#define K_DIM   2048
#define EMB     768
#define TAUF    32.0f
#define NROWS   192
#define KC      32            // bf16 K per chunk
#define NCH     (K_DIM / KC)  // 64

__device__ __align__(16) unsigned short g_Bh[NROWS * K_DIM];
__device__ __align__(16) unsigned short g_Bl[NROWS * K_DIM];

// ---------------- helpers ----------------
__device__ __forceinline__ uint32_t smem_u32(const void* p) {
    uint32_t a;
    asm("{ .reg .u64 t; cvta.to.shared.u64 t, %1; cvt.u32.u64 %0, t; }" : "=r"(a) : "l"(p));
    return a;
}
__device__ __forceinline__ unsigned long long dup2(float x) {
    unsigned long long r; asm("mov.b64 %0, {%1, %1};" : "=l"(r) : "f"(x)); return r;
}
__device__ __forceinline__ void ffma2(unsigned long long& d, unsigned long long a,
                                      unsigned long long b) {
    asm("fma.rn.f32x2 %0, %1, %2, %0;" : "+l"(d) : "l"(a), "l"(b));
}
__device__ __forceinline__ float2 unpack2(unsigned long long v) {
    float2 f; asm("mov.b64 {%0, %1}, %2;" : "=f"(f.x), "=f"(f.y) : "l"(v)); return f;
}
__device__ __forceinline__ uint32_t cvt_bf16x2(float lo, float hi) {
    uint32_t r; asm("cvt.rn.bf16x2.f32 %0, %1, %2;" : "=r"(r) : "f"(hi), "f"(lo)); return r;
}
__device__ __forceinline__ void ldsm4(uint32_t* r, uint32_t addr) {
    asm volatile("ldmatrix.sync.aligned.m8n8.x4.shared.b16 {%0,%1,%2,%3}, [%4];"
                 : "=r"(r[0]), "=r"(r[1]), "=r"(r[2]), "=r"(r[3]) : "r"(addr));
}
__device__ __forceinline__ void mma16816(float* d, const uint32_t* a, const uint32_t* b) {
    asm volatile("mma.sync.aligned.m16n8k16.row.col.f32.bf16.bf16.f32 "
                 "{%0,%1,%2,%3}, {%4,%5,%6,%7}, {%8,%9}, {%0,%1,%2,%3};"
                 : "+f"(d[0]), "+f"(d[1]), "+f"(d[2]), "+f"(d[3])
                 : "r"(a[0]), "r"(a[1]), "r"(a[2]), "r"(a[3]), "r"(b[0]), "r"(b[1]));
}
#define CP16(dst, src)  asm volatile("cp.async.cg.shared.global [%0], [%1], 16;" \
                                     :: "r"(dst), "l"(src) : "memory")
#define CP_COMMIT()     asm volatile("cp.async.commit_group;" ::: "memory")
#define CP_WAIT0()      asm volatile("cp.async.wait_group 0;" ::: "memory")

// ----------------------------------------------------------------------------
// Kernel A: M[row][k] = sum_e mem[row][e] * W[e][k], bf16 hi/lo out.
// grid (64 kx, 2 mtx) = 128 blocks, 256 thr = 32 kcols x 8 rowgroups(12 rows).
// mem tile staged in smem in 6 chunks of 128 e; W read exactly once.
// ----------------------------------------------------------------------------
#define ECH 128

__global__ void __launch_bounds__(256) build_M_kernel(
    const float* __restrict__ Wt, const float* __restrict__ Wd,
    const float* __restrict__ memtab, const void* __restrict__ catp)
{
    __shared__ __align__(16) float memsm[ECH][96];   // 49152 B

    const int tid  = threadIdx.x;
    const int kcol = tid & 31;
    const int rg   = tid >> 5;          // 0..7
    const int kx   = blockIdx.x;        // 0..63
    const int mtx  = blockIdx.y;        // 0..1
    const int k    = kx * 32 + kcol;
    const int base_row = mtx * 96;

    const int* c32 = (const int*)catp;
    bool is64 = true;
    #pragma unroll
    for (int j = 0; j < 9; j++) if (c32[2 * j + 1] != 0) is64 = false;
    int catv[9];
    #pragma unroll
    for (int j = 0; j < 9; j++)
        catv[j] = is64 ? (int)(((const long long*)catp)[j]) : c32[j];

    const float* W = mtx ? Wd : Wt;

    unsigned long long acc[6];
    #pragma unroll
    for (int j = 0; j < 6; j++) acc[j] = 0ull;

    for (int ec = 0; ec < EMB / ECH; ec++) {
        const int e0 = ec * ECH;
        // stage mem rows [96][128 e] (row-major in smem as [e][96])
        for (int idx = tid; idx < 96 * ECH; idx += 256) {
            int e = idx & (ECH - 1), row = idx >> 7;
            float v = 0.0f;
            if (row < 90) {
                int d = row / 10, m = row % 10;
                v = memtab[(catv[d] * 10 + m) * EMB + e0 + e];
            }
            memsm[e][row] = v;
        }
        __syncthreads();

        #pragma unroll 4
        for (int e = 0; e < ECH; e++) {
            unsigned long long wd = dup2(W[(size_t)(e0 + e) * K_DIM + k]);
            const ulonglong2* mr = (const ulonglong2*)(&memsm[e][rg * 12]);
            ulonglong2 p0 = mr[0], p1 = mr[1], p2 = mr[2];
            ffma2(acc[0], p0.x, wd); ffma2(acc[1], p0.y, wd);
            ffma2(acc[2], p1.x, wd); ffma2(acc[3], p1.y, wd);
            ffma2(acc[4], p2.x, wd); ffma2(acc[5], p2.y, wd);
        }
        __syncthreads();
    }

    #pragma unroll
    for (int j = 0; j < 6; j++) {
        float2 v = unpack2(acc[j]);
        float vv[2] = {v.x, v.y};
        #pragma unroll
        for (int h = 0; h < 2; h++) {
            float s = vv[h];
            uint32_t u = __float_as_uint(s);
            float hif = __uint_as_float(u & 0xFFFF0000u);
            float lo  = s - hif;
            __nv_bfloat16 lb = __float2bfloat16(lo);
            size_t off = (size_t)(base_row + rg * 12 + 2 * j + h) * K_DIM + k;
            g_Bh[off] = (unsigned short)(u >> 16);
            g_Bl[off] = *(unsigned short*)&lb;
        }
    }
}

// ----------------------------------------------------------------------------
// Fused mma.sync GEMM + norms + softmaxes
// grid 256 CTAs x 256 threads (8 warps as 2x4); per-CTA tile M=64, N=192.
// KC=32 double buffer, mma-first schedule, 2 CTAs/SM.
// Per buffer (stride 80 B rows): Ah/Al 64x80 (5120 ea), Bh/Bl 192x80 (15360 ea)
// ----------------------------------------------------------------------------
#define BM       64
#define LDSB     80                          // bytes per row (32 bf16 + pad)
#define AH_OFF   0
#define AL_OFF   5120
#define BH_OFF   10240
#define BL_OFF   25600
#define BUF_STR  40960
#define CS_LD    194
#define RS_OFF   (2 * BUF_STR)               // 81920 (> Cs = 64*194*4 = 49664)
#define SMEM_TOT (RS_OFF + BM * 4)           // 82176

__global__ void __launch_bounds__(256, 2) fused_kernel(
    const float* __restrict__ feat, float* __restrict__ out)
{
    extern __shared__ __align__(16) char smem[];
    const uint32_t sbase = smem_u32(smem);
    float* Cs     = (float*)smem;
    float* rowsum = (float*)(smem + RS_OFF);

    const int tid  = threadIdx.x;
    const int lane = tid & 31;
    const int wid  = tid >> 5;
    const int wr   = wid >> 2;      // 0..1 -> 32-row band
    const int wc   = wid & 3;       // 0..3 -> 48-col band
    const int b0   = blockIdx.x * BM;

    if (tid < BM) rowsum[tid] = 0.0f;

    float acc[2][6][4];
    #pragma unroll
    for (int i = 0; i < 2; i++)
        #pragma unroll
        for (int j = 0; j < 6; j++)
            #pragma unroll
            for (int q = 0; q < 4; q++) acc[i][j][q] = 0.0f;

    float ss = 0.0f;
    float4 aregs[2];
    const int ar = tid >> 2;        // row 0..63
    const int ac = tid & 3;         // 8-float segment 0..3

    auto ldgA = [&](int kc) {
        const float4* src = (const float4*)(feat + (size_t)(b0 + ar) * K_DIM + kc + ac * 8);
        aregs[0] = src[0];
        aregs[1] = src[1];
    };
    auto stsA = [&](uint32_t bufo) {
        float4 v0 = aregs[0], v1 = aregs[1];
        float f[8] = {v0.x, v0.y, v0.z, v0.w, v1.x, v1.y, v1.z, v1.w};
        ss += f[0]*f[0] + f[1]*f[1] + f[2]*f[2] + f[3]*f[3]
            + f[4]*f[4] + f[5]*f[5] + f[6]*f[6] + f[7]*f[7];
        uint32_t hi[4], lo[4];
        #pragma unroll
        for (int p = 0; p < 4; p++) {
            uint32_t u0 = __float_as_uint(f[2*p]), u1 = __float_as_uint(f[2*p+1]);
            hi[p] = (u0 >> 16) | (u1 & 0xFFFF0000u);
            float l0 = f[2*p]   - __uint_as_float(u0 & 0xFFFF0000u);
            float l1 = f[2*p+1] - __uint_as_float(u1 & 0xFFFF0000u);
            lo[p] = cvt_bf16x2(l0, l1);
        }
        uint32_t boff = bufo + (uint32_t)(ar * LDSB + ac * 16);
        *(uint4*)(smem + AH_OFF + boff) = make_uint4(hi[0], hi[1], hi[2], hi[3]);
        *(uint4*)(smem + AL_OFF + boff) = make_uint4(lo[0], lo[1], lo[2], lo[3]);
    };
    auto cpB = [&](int kc, uint32_t bufo) {
        #pragma unroll
        for (int l = 0; l < 3; l++) {
            int ci = tid + 256 * l;          // 0..767
            int r = ci >> 2, cc = ci & 3;
            size_t g = (size_t)r * K_DIM + kc + cc * 8;
            uint32_t d = sbase + bufo + (uint32_t)(r * LDSB + cc * 16);
            CP16(d + BH_OFF, g_Bh + g);
            CP16(d + BL_OFF, g_Bl + g);
        }
    };

    const int mbase = wr * 32;
    const int nbase = wc * 48;

    auto doK16 = [&](int k16, uint32_t rbuf) {
        const uint32_t akoff = (uint32_t)(k16 * 16 + (lane >> 4) * 8) * 2;
        const uint32_t bkoff = (uint32_t)(k16 * 16 + ((lane >> 3) & 1) * 8) * 2;

        uint32_t ah[2][4], al[2][4];
        #pragma unroll
        for (int mt = 0; mt < 2; mt++) {
            uint32_t rowb = (uint32_t)(mbase + mt * 16 + (lane & 15)) * LDSB;
            ldsm4(ah[mt], sbase + rbuf + AH_OFF + rowb + akoff);
            ldsm4(al[mt], sbase + rbuf + AL_OFF + rowb + akoff);
        }
        uint32_t bh[3][4];
        #pragma unroll
        for (int bt = 0; bt < 3; bt++) {
            uint32_t rowb = (uint32_t)(nbase + bt * 16 + (lane & 7) + ((lane >> 4) << 3))
                          * LDSB;
            ldsm4(bh[bt], sbase + rbuf + BH_OFF + rowb + bkoff);
        }
        #pragma unroll
        for (int mt = 0; mt < 2; mt++)
            #pragma unroll
            for (int nt = 0; nt < 6; nt++) {
                mma16816(acc[mt][nt], ah[mt], &bh[nt >> 1][(nt & 1) * 2]);
                mma16816(acc[mt][nt], al[mt], &bh[nt >> 1][(nt & 1) * 2]);
            }
        uint32_t bl[3][4];
        #pragma unroll
        for (int bt = 0; bt < 3; bt++) {
            uint32_t rowb = (uint32_t)(nbase + bt * 16 + (lane & 7) + ((lane >> 4) << 3))
                          * LDSB;
            ldsm4(bl[bt], sbase + rbuf + BL_OFF + rowb + bkoff);
        }
        #pragma unroll
        for (int mt = 0; mt < 2; mt++)
            #pragma unroll
            for (int nt = 0; nt < 6; nt++)
                mma16816(acc[mt][nt], ah[mt], &bl[nt >> 1][(nt & 1) * 2]);
    };

    // ---- prologue: chunk 0 into buf0; prefetch chunk 1's A into regs ----
    ldgA(0);
    cpB(0, 0);
    CP_COMMIT();
    stsA(0);           // consumes chunk 0 from aregs
    ldgA(KC);          // aregs <- chunk 1 (chunk 0 already stored)
    CP_WAIT0();
    __syncthreads();

    for (int c = 0; c < NCH; c++) {
        const uint32_t rbuf = (uint32_t)(c & 1) * BUF_STR;
        const uint32_t wbuf = rbuf ^ BUF_STR;

        doK16(0, rbuf);                           // prime the tensor pipe

        if (c + 1 < NCH) {
            cpB((c + 1) * KC, wbuf);              // async B for next chunk
            CP_COMMIT();
            stsA(wbuf);                           // consume aregs (chunk c+1) FIRST
            if (c + 2 < NCH) ldgA((c + 2) * KC);  // THEN refill; hides under mma
        }

        doK16(1, rbuf);

        CP_WAIT0();
        __syncthreads();
    }

    // ---- C fragments -> smem (buffers reused) ----
    #pragma unroll
    for (int mt = 0; mt < 2; mt++)
        #pragma unroll
        for (int nt = 0; nt < 6; nt++) {
            int row = wr * 32 + mt * 16 + (lane >> 2);
            int col = wc * 48 + nt * 8 + (lane & 3) * 2;
            *(float2*)&Cs[row * CS_LD + col]       = make_float2(acc[mt][nt][0], acc[mt][nt][1]);
            *(float2*)&Cs[(row + 8) * CS_LD + col] = make_float2(acc[mt][nt][2], acc[mt][nt][3]);
        }
    atomicAdd(&rowsum[ar], ss);
    __syncthreads();

    // ---- per-row softmax chain ----
    if (tid < BM) {
        const int    b  = b0 + tid;
        const float  s  = TAUF / fmaxf(sqrtf(rowsum[tid]), 1e-12f);
        const float* cr = Cs + tid * CS_LD;

        float L[9];
        #pragma unroll
        for (int d = 0; d < 9; d++) {
            float mx = -1e30f;
            #pragma unroll
            for (int m = 0; m < 10; m++) mx = fmaxf(mx, cr[d * 10 + m]);
            float se = 0.f, ac2 = 0.f;
            #pragma unroll
            for (int m = 0; m < 10; m++) {
                float e = expf(s * (cr[d * 10 + m] - mx));
                se += e;
                ac2 += e * cr[96 + d * 10 + m];
            }
            L[d] = s * ac2 / se;
        }
        float mx2 = -1e30f;
        #pragma unroll
        for (int d = 0; d < 9; d++) mx2 = fmaxf(mx2, L[d]);
        float ex[9], s2 = 0.f;
        #pragma unroll
        for (int d = 0; d < 9; d++) { ex[d] = expf(L[d] - mx2); s2 += ex[d]; }
        const float inv = 1.0f / s2;
        #pragma unroll
        for (int d = 0; d < 9; d++) out[b * 9 + d] = ex[d] * inv;
    }
}

// ----------------------------------------------------------------------------
extern "C" void kernel_launch(void* const* d_in, const int* in_sizes, int n_in,
                              void* d_out, int out_size)
{
    const float* feature = (const float*)d_in[0];  // (16384, 2048)
    const float* Wt      = (const float*)d_in[1];  // (768, 2048)
    const float* Wd      = (const float*)d_in[2];  // (768, 2048)
    const float* memtab  = (const float*)d_in[3];  // (9, 10, 768)
    const void*  cat     = d_in[4];                // (16384,) int32/int64

    cudaFuncSetAttribute(fused_kernel,
                         cudaFuncAttributeMaxDynamicSharedMemorySize, SMEM_TOT);

    dim3 gA(64, 2);
    build_M_kernel<<<gA, 256>>>(Wt, Wd, memtab, cat);
    fused_kernel<<<16384 / BM, 256, SMEM_TOT>>>(feature, (float*)d_out);
}

// round 15
// speedup vs baseline: 2.0098x; 2.0098x over previous
#include <cuda_runtime.h>
#include <cuda_bf16.h>
#include <math.h>
#include <stdint.h>

// ----------------------------------------------------------------------------
// MemoryNetwork, GB300 sm_103a (PTX target sm_103 => family-portable ISA only)
//
//   M1[d,m,:] = W_topic  @ mems_d[d,m]; M2 likewise (rows 0..95 topic, 96..191 domain)
//   P[b,r]    = feature_b . M[r]   via mma.sync bf16 hi/lo split (3 passes, fp32 acc)
//   fused row-norm + topic softmax + domain softmax epilogue.
//
// R13 == R12 resubmitted (previous round died to container infra, not the kernel):
//      fused kernel = R11 verbatim (measured 112.7us).
//      build_M: 512 blocks, in-block split-K (4 e-groups), W staged via
//      cp.async double buffer => W-load latency off the critical path.
// ----------------------------------------------------------------------------

#define K_DIM   2048
#define EMB     768
#define TAUF    32.0f
#define NROWS   192
#define KC      32            // bf16 K per chunk (fused kernel)
#define NCH     (K_DIM / KC)  // 64

__device__ __align__(16) unsigned short g_Bh[NROWS * K_DIM];
__device__ __align__(16) unsigned short g_Bl[NROWS * K_DIM];

// ---------------- helpers ----------------
__device__ __forceinline__ uint32_t smem_u32(const void* p) {
    uint32_t a;
    asm("{ .reg .u64 t; cvta.to.shared.u64 t, %1; cvt.u32.u64 %0, t; }" : "=r"(a) : "l"(p));
    return a;
}
__device__ __forceinline__ unsigned long long dup2(float x) {
    unsigned long long r; asm("mov.b64 %0, {%1, %1};" : "=l"(r) : "f"(x)); return r;
}
__device__ __forceinline__ void ffma2(unsigned long long& d, unsigned long long a,
                                      unsigned long long b) {
    asm("fma.rn.f32x2 %0, %1, %2, %0;" : "+l"(d) : "l"(a), "l"(b));
}
__device__ __forceinline__ float2 unpack2(unsigned long long v) {
    float2 f; asm("mov.b64 {%0, %1}, %2;" : "=f"(f.x), "=f"(f.y) : "l"(v)); return f;
}
__device__ __forceinline__ uint32_t cvt_bf16x2(float lo, float hi) {
    uint32_t r; asm("cvt.rn.bf16x2.f32 %0, %1, %2;" : "=r"(r) : "f"(hi), "f"(lo)); return r;
}
__device__ __forceinline__ void ldsm4(uint32_t* r, uint32_t addr) {
    asm volatile("ldmatrix.sync.aligned.m8n8.x4.shared.b16 {%0,%1,%2,%3}, [%4];"
                 : "=r"(r[0]), "=r"(r[1]), "=r"(r[2]), "=r"(r[3]) : "r"(addr));
}
__device__ __forceinline__ void mma16816(float* d, const uint32_t* a, const uint32_t* b) {
    asm volatile("mma.sync.aligned.m16n8k16.row.col.f32.bf16.bf16.f32 "
                 "{%0,%1,%2,%3}, {%4,%5,%6,%7}, {%8,%9}, {%0,%1,%2,%3};"
                 : "+f"(d[0]), "+f"(d[1]), "+f"(d[2]), "+f"(d[3])
                 : "r"(a[0]), "r"(a[1]), "r"(a[2]), "r"(a[3]), "r"(b[0]), "r"(b[1]));
}
#define CP16(dst, src)  asm volatile("cp.async.cg.shared.global [%0], [%1], 16;" \
                                     :: "r"(dst), "l"(src) : "memory")
#define CP_COMMIT()     asm volatile("cp.async.commit_group;" ::: "memory")
#define CP_WAIT0()      asm volatile("cp.async.wait_group 0;" ::: "memory")
#define CP_WAIT1()      asm volatile("cp.async.wait_group 1;" ::: "memory")

// ----------------------------------------------------------------------------
// Kernel A: M[row][k] = sum_e mem[row][e] * W[e][k], bf16 hi/lo out.
// grid (32 kx, 16 ry) = 512 blocks, 256 thr = 64 kcols x 4 egroups (192 e each).
// W staged via cp.async double buffer (6 stages of [128 packed e][64 k] fp32);
// in-block split-K reduce via SMEM partials. Deterministic.
// SMEM: memsm [768][12] f32 @0 (36864) | Wsm 2 x 32768 @36864 (partials overlay)
// ----------------------------------------------------------------------------
#define A_MEM_OFF  0
#define A_WS_OFF   36864
#define A_WBUF     32768
#define A_SMEM_TOT (A_WS_OFF + 2 * A_WBUF)   // 102400

__global__ void __launch_bounds__(256) build_M_kernel(
    const float* __restrict__ Wt, const float* __restrict__ Wd,
    const float* __restrict__ memtab, const void* __restrict__ catp)
{
    extern __shared__ __align__(16) char asm_smem[];
    const uint32_t sbase = smem_u32(asm_smem);
    float* memsm = (float*)(asm_smem + A_MEM_OFF);     // [e][12], 48 B rows
    float* part  = (float*)(asm_smem + A_WS_OFF);      // [4][64][12] after compute

    const int tid = threadIdx.x;
    const int kl  = tid & 63;          // k column 0..63
    const int eg  = tid >> 6;          // e-group 0..3 (192 e each)
    const int kx  = blockIdx.x;        // 0..31
    const int ry  = blockIdx.y;        // 0..15
    const int mtx = ry >> 3;
    const int grp = ry & 7;
    const int base_row = mtx * 96 + grp * 12;

    const int* c32 = (const int*)catp;
    bool is64 = true;
    #pragma unroll
    for (int j = 0; j < 9; j++) if (c32[2 * j + 1] != 0) is64 = false;
    int catv[9];
    #pragma unroll
    for (int j = 0; j < 9; j++)
        catv[j] = is64 ? (int)(((const long long*)catp)[j]) : c32[j];

    const float* W = mtx ? Wd : Wt;

    // stage st: for each eg, W rows e = eg*192 + st*32 + i (i=0..31),
    // packed into Wsm[eg*32+i][64 cols]
    auto cpW = [&](int st, uint32_t bufo) {
        #pragma unroll
        for (int l = 0; l < 8; l++) {
            int ci   = tid + 256 * l;       // 0..2047
            int row  = ci >> 4;             // packed row 0..127
            int col4 = ci & 15;             // 16B unit
            int e    = (row >> 5) * 192 + st * 32 + (row & 31);
            CP16(sbase + A_WS_OFF + bufo + (uint32_t)(row * 256 + col4 * 16),
                 W + (size_t)e * K_DIM + kx * 64 + col4 * 4);
        }
    };

    // ---- prologue: stages 0,1 in flight; fill memsm meanwhile ----
    cpW(0, 0);
    CP_COMMIT();
    cpW(1, A_WBUF);
    CP_COMMIT();

    for (int idx = tid; idx < 12 * EMB; idx += 256) {
        int rr = idx / EMB, e = idx % EMB;
        int gr = grp * 12 + rr;
        float v = 0.0f;
        if (gr < 90) {
            int d = gr / 10, m = gr % 10;
            v = memtab[(catv[d] * 10 + m) * EMB + e];
        }
        memsm[e * 12 + rr] = v;
    }
    CP_WAIT1();
    __syncthreads();

    unsigned long long acc[6];
    #pragma unroll
    for (int j = 0; j < 6; j++) acc[j] = 0ull;

    for (int st = 0; st < 6; st++) {
        const uint32_t bufo = (uint32_t)(st & 1) * A_WBUF;
        const float* wbuf = (const float*)(asm_smem + A_WS_OFF + bufo);
        const int e0 = eg * 192 + st * 32;

        #pragma unroll
        for (int i = 0; i < 32; i++) {
            unsigned long long wd = dup2(wbuf[(eg * 32 + i) * 64 + kl]);
            const ulonglong2* mr = (const ulonglong2*)(memsm + (e0 + i) * 12);
            ulonglong2 p0 = mr[0], p1 = mr[1], p2 = mr[2];
            ffma2(acc[0], p0.x, wd); ffma2(acc[1], p0.y, wd);
            ffma2(acc[2], p1.x, wd); ffma2(acc[3], p1.y, wd);
            ffma2(acc[4], p2.x, wd); ffma2(acc[5], p2.y, wd);
        }
        __syncthreads();                        // all warps done reading this buffer
        if (st + 2 < 6) { cpW(st + 2, bufo); CP_COMMIT(); }
        if (st < 5) {
            if (st < 4) CP_WAIT1(); else CP_WAIT0();
            __syncthreads();
        }
    }

    // ---- split-K reduce via SMEM partials (Wsm region reused) ----
    __syncthreads();
    float vals[12];
    #pragma unroll
    for (int j = 0; j < 6; j++) {
        float2 v = unpack2(acc[j]);
        vals[2 * j] = v.x; vals[2 * j + 1] = v.y;
    }
    float* pp = part + (eg * 64 + kl) * 12;
    #pragma unroll
    for (int j = 0; j < 12; j++) pp[j] = vals[j];
    __syncthreads();

    #pragma unroll
    for (int o = tid; o < 768; o += 256) {
        int okl = o & 63, row = o >> 6;
        float s = part[(0 * 64 + okl) * 12 + row] + part[(1 * 64 + okl) * 12 + row]
                + part[(2 * 64 + okl) * 12 + row] + part[(3 * 64 + okl) * 12 + row];
        uint32_t u = __float_as_uint(s);
        float hif = __uint_as_float(u & 0xFFFF0000u);
        float lo  = s - hif;
        __nv_bfloat16 lb = __float2bfloat16(lo);
        size_t off = (size_t)(base_row + row) * K_DIM + kx * 64 + okl;
        g_Bh[off] = (unsigned short)(u >> 16);
        g_Bl[off] = *(unsigned short*)&lb;
    }
}

// ----------------------------------------------------------------------------
// Fused mma.sync GEMM + norms + softmaxes  (R11 verbatim — measured 112.7us)
// grid 256 CTAs x 256 threads (8 warps as 2x4); per-CTA tile M=64, N=192.
// KC=32 double buffer, mma-first schedule, 2 CTAs/SM.
// ----------------------------------------------------------------------------
#define BM       64
#define LDSB     80                          // bytes per row (32 bf16 + pad)
#define AH_OFF   0
#define AL_OFF   5120
#define BH_OFF   10240
#define BL_OFF   25600
#define BUF_STR  40960
#define CS_LD    194
#define RS_OFF   (2 * BUF_STR)               // 81920 (> Cs = 64*194*4 = 49664)
#define SMEM_TOT (RS_OFF + BM * 4)           // 82176

__global__ void __launch_bounds__(256, 2) fused_kernel(
    const float* __restrict__ feat, float* __restrict__ out)
{
    extern __shared__ __align__(16) char smem[];
    const uint32_t sbase = smem_u32(smem);
    float* Cs     = (float*)smem;
    float* rowsum = (float*)(smem + RS_OFF);

    const int tid  = threadIdx.x;
    const int lane = tid & 31;
    const int wid  = tid >> 5;
    const int wr   = wid >> 2;      // 0..1 -> 32-row band
    const int wc   = wid & 3;       // 0..3 -> 48-col band
    const int b0   = blockIdx.x * BM;

    if (tid < BM) rowsum[tid] = 0.0f;

    float acc[2][6][4];
    #pragma unroll
    for (int i = 0; i < 2; i++)
        #pragma unroll
        for (int j = 0; j < 6; j++)
            #pragma unroll
            for (int q = 0; q < 4; q++) acc[i][j][q] = 0.0f;

    float ss = 0.0f;
    float4 aregs[2];
    const int ar = tid >> 2;        // row 0..63
    const int ac = tid & 3;         // 8-float segment 0..3

    auto ldgA = [&](int kc) {
        const float4* src = (const float4*)(feat + (size_t)(b0 + ar) * K_DIM + kc + ac * 8);
        aregs[0] = src[0];
        aregs[1] = src[1];
    };
    auto stsA = [&](uint32_t bufo) {
        float4 v0 = aregs[0], v1 = aregs[1];
        float f[8] = {v0.x, v0.y, v0.z, v0.w, v1.x, v1.y, v1.z, v1.w};
        ss += f[0]*f[0] + f[1]*f[1] + f[2]*f[2] + f[3]*f[3]
            + f[4]*f[4] + f[5]*f[5] + f[6]*f[6] + f[7]*f[7];
        uint32_t hi[4], lo[4];
        #pragma unroll
        for (int p = 0; p < 4; p++) {
            uint32_t u0 = __float_as_uint(f[2*p]), u1 = __float_as_uint(f[2*p+1]);
            hi[p] = (u0 >> 16) | (u1 & 0xFFFF0000u);
            float l0 = f[2*p]   - __uint_as_float(u0 & 0xFFFF0000u);
            float l1 = f[2*p+1] - __uint_as_float(u1 & 0xFFFF0000u);
            lo[p] = cvt_bf16x2(l0, l1);
        }
        uint32_t boff = bufo + (uint32_t)(ar * LDSB + ac * 16);
        *(uint4*)(smem + AH_OFF + boff) = make_uint4(hi[0], hi[1], hi[2], hi[3]);
        *(uint4*)(smem + AL_OFF + boff) = make_uint4(lo[0], lo[1], lo[2], lo[3]);
    };
    auto cpB = [&](int kc, uint32_t bufo) {
        #pragma unroll
        for (int l = 0; l < 3; l++) {
            int ci = tid + 256 * l;          // 0..767
            int r = ci >> 2, cc = ci & 3;
            size_t g = (size_t)r * K_DIM + kc + cc * 8;
            uint32_t d = sbase + bufo + (uint32_t)(r * LDSB + cc * 16);
            CP16(d + BH_OFF, g_Bh + g);
            CP16(d + BL_OFF, g_Bl + g);
        }
    };

    const int mbase = wr * 32;
    const int nbase = wc * 48;

    auto doK16 = [&](int k16, uint32_t rbuf) {
        const uint32_t akoff = (uint32_t)(k16 * 16 + (lane >> 4) * 8) * 2;
        const uint32_t bkoff = (uint32_t)(k16 * 16 + ((lane >> 3) & 1) * 8) * 2;

        uint32_t ah[2][4], al[2][4];
        #pragma unroll
        for (int mt = 0; mt < 2; mt++) {
            uint32_t rowb = (uint32_t)(mbase + mt * 16 + (lane & 15)) * LDSB;
            ldsm4(ah[mt], sbase + rbuf + AH_OFF + rowb + akoff);
            ldsm4(al[mt], sbase + rbuf + AL_OFF + rowb + akoff);
        }
        uint32_t bh[3][4];
        #pragma unroll
        for (int bt = 0; bt < 3; bt++) {
            uint32_t rowb = (uint32_t)(nbase + bt * 16 + (lane & 7) + ((lane >> 4) << 3))
                          * LDSB;
            ldsm4(bh[bt], sbase + rbuf + BH_OFF + rowb + bkoff);
        }
        #pragma unroll
        for (int mt = 0; mt < 2; mt++)
            #pragma unroll
            for (int nt = 0; nt < 6; nt++) {
                mma16816(acc[mt][nt], ah[mt], &bh[nt >> 1][(nt & 1) * 2]);
                mma16816(acc[mt][nt], al[mt], &bh[nt >> 1][(nt & 1) * 2]);
            }
        uint32_t bl[3][4];
        #pragma unroll
        for (int bt = 0; bt < 3; bt++) {
            uint32_t rowb = (uint32_t)(nbase + bt * 16 + (lane & 7) + ((lane >> 4) << 3))
                          * LDSB;
            ldsm4(bl[bt], sbase + rbuf + BL_OFF + rowb + bkoff);
        }
        #pragma unroll
        for (int mt = 0; mt < 2; mt++)
            #pragma unroll
            for (int nt = 0; nt < 6; nt++)
                mma16816(acc[mt][nt], ah[mt], &bl[nt >> 1][(nt & 1) * 2]);
    };

    // ---- prologue: chunk 0 into buf0; prefetch chunk 1's A into regs ----
    ldgA(0);
    cpB(0, 0);
    CP_COMMIT();
    stsA(0);           // consumes chunk 0 from aregs
    ldgA(KC);          // aregs <- chunk 1 (chunk 0 already stored)
    CP_WAIT0();
    __syncthreads();

    for (int c = 0; c < NCH; c++) {
        const uint32_t rbuf = (uint32_t)(c & 1) * BUF_STR;
        const uint32_t wbuf = rbuf ^ BUF_STR;

        doK16(0, rbuf);                           // prime the tensor pipe

        if (c + 1 < NCH) {
            cpB((c + 1) * KC, wbuf);              // async B for next chunk
            CP_COMMIT();
            stsA(wbuf);                           // consume aregs (chunk c+1) FIRST
            if (c + 2 < NCH) ldgA((c + 2) * KC);  // THEN refill; hides under mma
        }

        doK16(1, rbuf);

        CP_WAIT0();
        __syncthreads();
    }

    // ---- C fragments -> smem (buffers reused) ----
    #pragma unroll
    for (int mt = 0; mt < 2; mt++)
        #pragma unroll
        for (int nt = 0; nt < 6; nt++) {
            int row = wr * 32 + mt * 16 + (lane >> 2);
            int col = wc * 48 + nt * 8 + (lane & 3) * 2;
            *(float2*)&Cs[row * CS_LD + col]       = make_float2(acc[mt][nt][0], acc[mt][nt][1]);
            *(float2*)&Cs[(row + 8) * CS_LD + col] = make_float2(acc[mt][nt][2], acc[mt][nt][3]);
        }
    atomicAdd(&rowsum[ar], ss);
    __syncthreads();

    // ---- per-row softmax chain ----
    if (tid < BM) {
        const int    b  = b0 + tid;
        const float  s  = TAUF / fmaxf(sqrtf(rowsum[tid]), 1e-12f);
        const float* cr = Cs + tid * CS_LD;

        float L[9];
        #pragma unroll
        for (int d = 0; d < 9; d++) {
            float mx = -1e30f;
            #pragma unroll
            for (int m = 0; m < 10; m++) mx = fmaxf(mx, cr[d * 10 + m]);
            float se = 0.f, ac2 = 0.f;
            #pragma unroll
            for (int m = 0; m < 10; m++) {
                float e = expf(s * (cr[d * 10 + m] - mx));
                se += e;
                ac2 += e * cr[96 + d * 10 + m];
            }
            L[d] = s * ac2 / se;
        }
        float mx2 = -1e30f;
        #pragma unroll
        for (int d = 0; d < 9; d++) mx2 = fmaxf(mx2, L[d]);
        float ex[9], s2 = 0.f;
        #pragma unroll
        for (int d = 0; d < 9; d++) { ex[d] = expf(L[d] - mx2); s2 += ex[d]; }
        const float inv = 1.0f / s2;
        #pragma unroll
        for (int d = 0; d < 9; d++) out[b * 9 + d] = ex[d] * inv;
    }
}

// ----------------------------------------------------------------------------
extern "C" void kernel_launch(void* const* d_in, const int* in_sizes, int n_in,
                              void* d_out, int out_size)
{
    const float* feature = (const float*)d_in[0];  // (16384, 2048)
    const float* Wt      = (const float*)d_in[1];  // (768, 2048)
    const float* Wd      = (const float*)d_in[2];  // (768, 2048)
    const float* memtab  = (const float*)d_in[3];  // (9, 10, 768)
    const void*  cat     = d_in[4];                // (16384,) int32/int64

    cudaFuncSetAttribute(build_M_kernel,
                         cudaFuncAttributeMaxDynamicSharedMemorySize, A_SMEM_TOT);
    cudaFuncSetAttribute(fused_kernel,
                         cudaFuncAttributeMaxDynamicSharedMemorySize, SMEM_TOT);

    dim3 gA(32, 16);
    build_M_kernel<<<gA, 256, A_SMEM_TOT>>>(Wt, Wd, memtab, cat);
    fused_kernel<<<16384 / BM, 256, SMEM_TOT>>>(feature, (float*)d_out);
}